// round 10
// baseline (speedup 1.0000x reference)
#include <cuda_runtime.h>
#include <math.h>

#define G 128
#define NPG0 256
#define NNODE (G*NPG0)      // 32768
#define NF 128
#define EPG 4096
#define NE (G*EPG)          // 524288
#define KCONV (NF*9)        // 1152
#define KFC (256*9)         // 2304
#define CH 8                // inputs per K-chunk in kan_gemm
#define KR (CH*9)           // 72 K-rows per chunk
#define WSP 132             // padded Ws stride in input_linear (bank-conflict fix)

// ---------------- scratch (device globals; no allocation) ----------------
// INVARIANT: these symbols are referenced from DEVICE code only. Host code
// passing &d_xxx passes the host shadow address (UB -> 128MiB driver alloc
// that trips _HX_ENFORCE). Host selects buffers via the `lev` integer.
__device__ float d_xbuf[NNODE*NF];          // 16 MiB
__device__ float d_agg [NNODE*NF];          // 16 MiB (gemm writes back in place)
__device__ int   d_srcA[NE];                // 2 MiB
__device__ int   d_dstA[NE];                // 2 MiB
__device__ int   d_srcB[NE];                // 2 MiB
__device__ int   d_dstB[NE];                // 2 MiB
__device__ int   d_ecntA[G];
__device__ int   d_ecntB[G];
__device__ float d_read[2*3*G*256];         // 0.75 MiB
__device__ float d_wconvT[6*KCONV*NF];      // 3.4 MiB
__device__ float d_wfcgT[2*KFC*256];        // 4.5 MiB
__device__ float d_wfinT[2*KFC];
__device__ float d_xg[2*G*256];

// ---------------- packed f32x2 helpers (sm_100+ PTX) ----------------
__device__ __forceinline__ unsigned long long pk2(float lo, float hi){
    unsigned long long r;
    asm("mov.b64 %0, {%1, %2};" : "=l"(r) : "f"(lo), "f"(hi));
    return r;
}
__device__ __forceinline__ void upk2(unsigned long long v, float& lo, float& hi){
    asm("mov.b64 {%0, %1}, %2;" : "=f"(lo), "=f"(hi) : "l"(v));
}
__device__ __forceinline__ void ffma2(unsigned long long& acc, unsigned long long a,
                                      unsigned long long b){
    asm("fma.rn.f32x2 %0, %1, %2, %0;" : "+l"(acc) : "l"(a), "l"(b));
}

// ---------------- B-spline basis (cubic, GRID=5, 8 outputs) ----------------
__device__ __forceinline__ float knot(int j){ return (float)(j-3)*0.4f - 1.0f; }

__device__ __forceinline__ void bsplines8(float x, float* out){
    float b[11];
#pragma unroll
    for (int j = 0; j < 11; j++){
        float g0 = knot(j), g1 = knot(j+1);
        b[j] = (x >= g0 && x < g1) ? 1.0f : 0.0f;
    }
#pragma unroll
    for (int k = 1; k <= 3; k++){
#pragma unroll
        for (int j = 0; j <= 10-k; j++){
            float gj  = knot(j),     gjk  = knot(j+k);
            float gj1 = knot(j+1),   gjk1 = knot(j+k+1);
            b[j] = (x - gj)*(1.0f/(gjk - gj))*b[j]
                 + (gjk1 - x)*(1.0f/(gjk1 - gj1))*b[j+1];
        }
    }
#pragma unroll
    for (int j = 0; j < 8; j++) out[j] = b[j];
}

// ---------------- weight prep (transpose to [K][out]) ----------------
__global__ void prep_conv(const float* __restrict__ bw, const float* __restrict__ sw){
    int idx = blockIdx.x*blockDim.x + threadIdx.x;
    if (idx >= 6*KCONV*NF) return;
    int o = idx % NF;
    int kk = (idx / NF) % KCONV;
    int l = idx / (NF*KCONV);
    int i = kk / 9, s = kk % 9;
    float v = (s==0) ? bw[(l*NF + o)*NF + i]
                     : sw[((l*NF + o)*NF + i)*8 + (s-1)];
    d_wconvT[idx] = v;
}
__global__ void prep_fcg(const float* __restrict__ bw, const float* __restrict__ sw){
    int idx = blockIdx.x*blockDim.x + threadIdx.x;
    if (idx >= 2*KFC*256) return;
    int o = idx % 256;
    int kk = (idx / 256) % KFC;
    int l = idx / (256*KFC);
    int i = kk / 9, s = kk % 9;
    float v = (s==0) ? bw[(l*256 + o)*256 + i]
                     : sw[((l*256 + o)*256 + i)*8 + (s-1)];
    d_wfcgT[idx] = v;
}
__global__ void prep_fin(const float* __restrict__ bw, const float* __restrict__ sw){
    int idx = blockIdx.x*blockDim.x + threadIdx.x;
    if (idx >= 2*KFC) return;
    int kk = idx % KFC;
    int l = idx / KFC;
    int i = kk / 9, s = kk % 9;
    float v = (s==0) ? bw[l*256 + i] : sw[(l*256 + i)*8 + (s-1)];
    d_wfinT[idx] = v;
}

// ---------------- input linear: x = feat @ w.T + b -> d_xbuf ----------------
__global__ void __launch_bounds__(256) input_linear(
        const float* __restrict__ feat, const float* __restrict__ w,
        const float* __restrict__ bias, int IN){
    extern __shared__ float sm[];
    float* As = sm;              // [64][96]
    float* Ws = sm + 64*96;      // [96][WSP]  (row = input i; padded stride kills conflicts)
    int tid = threadIdx.x;
    int nbase = blockIdx.x * 64;
    for (int idx = tid; idx < 64*IN; idx += 256){
        int n = idx / IN, i = idx % IN;
        As[n*96 + i] = feat[(size_t)(nbase+n)*IN + i];
    }
    for (int idx = tid; idx < NF*IN; idx += 256){
        int o = idx / IN, i = idx % IN;
        Ws[i*WSP + o] = w[idx];
    }
    __syncthreads();
    int ng = (tid >> 5) * 8;
    int og = (tid & 31) * 4;
    unsigned long long acc[4][4];
#pragma unroll
    for (int p = 0; p < 4; p++)
#pragma unroll
        for (int c = 0; c < 4; c++) acc[p][c] = 0ull;
    for (int k = 0; k < IN; k++){
        float4 w4 = *(float4*)&Ws[k*WSP + og];
        unsigned long long w0 = pk2(w4.x, w4.x), w1 = pk2(w4.y, w4.y);
        unsigned long long w2 = pk2(w4.z, w4.z), w3 = pk2(w4.w, w4.w);
#pragma unroll
        for (int p = 0; p < 4; p++){
            unsigned long long a = pk2(As[(ng+2*p)*96 + k], As[(ng+2*p+1)*96 + k]);
            ffma2(acc[p][0], a, w0); ffma2(acc[p][1], a, w1);
            ffma2(acc[p][2], a, w2); ffma2(acc[p][3], a, w3);
        }
    }
    float4 b4 = *(float4*)&bias[og];
#pragma unroll
    for (int p = 0; p < 4; p++){
        float lo[4], hi[4];
#pragma unroll
        for (int c = 0; c < 4; c++) upk2(acc[p][c], lo[c], hi[c]);
        float4 v0; v0.x = lo[0]+b4.x; v0.y = lo[1]+b4.y; v0.z = lo[2]+b4.z; v0.w = lo[3]+b4.w;
        float4 v1; v1.x = hi[0]+b4.x; v1.y = hi[1]+b4.y; v1.z = hi[2]+b4.z; v1.w = hi[3]+b4.w;
        *(float4*)&d_xbuf[(size_t)(nbase+ng+2*p  )*NF + og] = v0;
        *(float4*)&d_xbuf[(size_t)(nbase+ng+2*p+1)*NF + og] = v1;
    }
}

// ---------------- GIN aggregation: agg = x + sum_{j->i} x_j (per-graph CTA) ----------------
// lev selects edge buffers in DEVICE code: 0 -> raw input ei (EPG edges),
// 1 -> compacted A buffers, 2 -> compacted B buffers.
__global__ void __launch_bounds__(256) aggregate(int n, int lev,
        const int* __restrict__ ei){
    extern __shared__ float xs[];                 // n*128 floats
    __shared__ int cnt[256];
    __shared__ int wo[256];
    __shared__ int scan[256];
    __shared__ int rowptr[257];
    __shared__ int csr[EPG];
    int g = blockIdx.x, tid = threadIdx.x;
    const int* esrc; const int* edst; int m;
    if (lev == 0){ esrc = ei;     edst = ei + NE; m = EPG; }
    else if (lev == 1){ esrc = d_srcA; edst = d_dstA; m = d_ecntA[g]; }
    else              { esrc = d_srcB; edst = d_dstB; m = d_ecntB[g]; }
    float4* xs4 = (float4*)xs;
    const float4* xin4 = (const float4*)d_xbuf;
    for (int idx = tid; idx < n*32; idx += 256)
        xs4[idx] = xin4[(size_t)g*n*32 + idx];
    cnt[tid] = 0; wo[tid] = 0;
    __syncthreads();
    int ebase = g*EPG;
    int nodebase = g*n;
    for (int e = tid; e < m; e += 256)
        atomicAdd(&cnt[edst[ebase+e] - nodebase], 1);
    __syncthreads();
    // parallel inclusive scan over 256 entries
    scan[tid] = cnt[tid];
    __syncthreads();
#pragma unroll
    for (int off = 1; off < 256; off <<= 1){
        int v = (tid >= off) ? scan[tid-off] : 0;
        __syncthreads();
        scan[tid] += v;
        __syncthreads();
    }
    rowptr[tid+1] = scan[tid];
    if (tid == 0) rowptr[0] = 0;
    __syncthreads();
    for (int e = tid; e < m; e += 256){
        int d = edst[ebase+e] - nodebase;
        int pos = rowptr[d] + atomicAdd(&wo[d], 1);
        csr[pos] = esrc[ebase+e] - nodebase;
    }
    __syncthreads();
    int wid = tid >> 5, lane = tid & 31;
    float4* agg4 = (float4*)d_agg;
    for (int i = wid; i < n; i += 8){
        float4 acc = xs4[i*32 + lane];
        int p1 = rowptr[i+1];
        for (int p = rowptr[i]; p < p1; p++){
            float4 v = xs4[csr[p]*32 + lane];
            acc.x += v.x; acc.y += v.y; acc.z += v.z; acc.w += v.w;
        }
        agg4[(size_t)(nodebase + i)*32 + lane] = acc;
    }
}

// ---------------- fused KAN conv GEMM + relu: d_agg <- relu([A|B(A)] @ W), IN PLACE ----
// A is staged DUPLICATED in smem (Ed[k][2n]=Ed[k][2n+1]=v) so packed FFMA2
// needs zero per-iteration MOVs: out-pairs come packed straight from Ws.
// Safe in-place: CTA owns rows nb..nb+63; reads complete before final barrier.
__global__ void __launch_bounds__(256) kan_gemm(int level){
    extern __shared__ float sm[];
    float* Ed = sm;            // [KR][128]  expanded A, each node value duplicated
    float* Ws = sm + KR*128;   // [KR][128]
    const float* __restrict__ W = d_wconvT + (size_t)level*KCONV*NF;
    int tid = threadIdx.x;
    int nb = blockIdx.x * 64;
    int ng = (tid >> 5) * 8;       // 8 warps x 8 rows
    int og = (tid & 31) * 4;       // 32 lanes x 4 outs (2 packed out-pairs)
    unsigned long long acc[8][2];
#pragma unroll
    for (int r = 0; r < 8; r++){ acc[r][0] = 0ull; acc[r][1] = 0ull; }

    for (int c = 0; c < NF/CH; c++){
        int i0 = c*CH;
        __syncthreads();
        // expand 64 nodes x CH inputs -> KR rows, duplicated (STS.64 conflict-free)
        for (int e = tid; e < 64*CH; e += 256){
            int nn = e & 63, ii = e >> 6;
            float xv = d_agg[(size_t)(nb+nn)*NF + i0 + ii];
            float bs[8]; bsplines8(xv, bs);
            *(unsigned long long*)&Ed[(ii*9)*128 + 2*nn] = pk2(xv, xv);
#pragma unroll
            for (int s = 0; s < 8; s++)
                *(unsigned long long*)&Ed[(ii*9+1+s)*128 + 2*nn] = pk2(bs[s], bs[s]);
        }
        {
            const float4* W4 = (const float4*)(W + (size_t)c*KR*128);
            float4* Ws4 = (float4*)Ws;
            for (int idx = tid; idx < KR*32; idx += 256)
                Ws4[idx] = W4[idx];
        }
        __syncthreads();
#pragma unroll 4
        for (int kk = 0; kk < KR; kk++){
            const float* Erow = &Ed[kk*128 + 2*ng];
            ulonglong2 a01 = *(const ulonglong2*)(Erow);       // rows ng, ng+1 (dup)
            ulonglong2 a23 = *(const ulonglong2*)(Erow + 4);   // rows ng+2, ng+3
            ulonglong2 a45 = *(const ulonglong2*)(Erow + 8);
            ulonglong2 a67 = *(const ulonglong2*)(Erow + 12);
            ulonglong2 w2 = *(const ulonglong2*)&Ws[kk*128 + og]; // pairs (og,og+1),(og+2,og+3)
            ffma2(acc[0][0], a01.x, w2.x); ffma2(acc[0][1], a01.x, w2.y);
            ffma2(acc[1][0], a01.y, w2.x); ffma2(acc[1][1], a01.y, w2.y);
            ffma2(acc[2][0], a23.x, w2.x); ffma2(acc[2][1], a23.x, w2.y);
            ffma2(acc[3][0], a23.y, w2.x); ffma2(acc[3][1], a23.y, w2.y);
            ffma2(acc[4][0], a45.x, w2.x); ffma2(acc[4][1], a45.x, w2.y);
            ffma2(acc[5][0], a45.y, w2.x); ffma2(acc[5][1], a45.y, w2.y);
            ffma2(acc[6][0], a67.x, w2.x); ffma2(acc[6][1], a67.x, w2.y);
            ffma2(acc[7][0], a67.y, w2.x); ffma2(acc[7][1], a67.y, w2.y);
        }
    }
#pragma unroll
    for (int r = 0; r < 8; r++){
        float o0, o1, o2, o3;
        upk2(acc[r][0], o0, o1);
        upk2(acc[r][1], o2, o3);
        float4 v;
        v.x = fmaxf(o0, 0.f); v.y = fmaxf(o1, 0.f);
        v.z = fmaxf(o2, 0.f); v.w = fmaxf(o3, 0.f);
        *(float4*)&d_agg[(size_t)(nb+ng+r)*NF + og] = v;
    }
}

// ---------------- fused pool + edge-compact + readout (per-graph CTA) ----------------
// reads conv output from d_agg; writes gated survivors to d_xbuf; [gmp|gap] to d_read.
// lev selects edge buffers in DEVICE code: in: 0->ei, 1->A, 2->B; out: 0->A, 1->B, 2->none.
__global__ void __launch_bounds__(256) pool_fused(int n, int k, const float* __restrict__ p,
        int b, int lev, const int* __restrict__ ei){
    __shared__ float s[256];
    __shared__ int pos[256];
    __shared__ unsigned char kf[256];
    __shared__ int maxv[128];
    __shared__ float sumv[128];
    __shared__ int ecnt_s;
    int g = blockIdx.x, tid = threadIdx.x;
    int wid = tid >> 5, lane = tid & 31;
    int nodebase = g*n;
    const int* esrcIn; const int* edstIn; int m;
    if (lev == 0){ esrcIn = ei;     edstIn = ei + NE; m = EPG; }
    else if (lev == 1){ esrcIn = d_srcA; edstIn = d_dstA; m = d_ecntA[g]; }
    else              { esrcIn = d_srcB; edstIn = d_dstB; m = d_ecntB[g]; }
    for (int i = wid; i < n; i += 8){
        float v = 0.f;
#pragma unroll
        for (int t = 0; t < 4; t++){
            int f = lane + t*32;
            v += d_agg[(size_t)(nodebase+i)*NF + f] * p[f];
        }
#pragma unroll
        for (int o = 16; o > 0; o >>= 1) v += __shfl_down_sync(0xffffffffu, v, o);
        if (lane == 0) s[i] = 1.0f/(1.0f + expf(-v));
    }
    if (tid < 128){ maxv[tid] = 0; sumv[tid] = 0.f; }
    if (tid == 0) ecnt_s = 0;
    __syncthreads();
    for (int i = tid; i < n; i += 256){
        float si = s[i]; int c = 0;
        for (int j = 0; j < n; j++){
            float sj = s[j];
            c += (sj > si) || (sj == si && j < i);
        }
        kf[i] = (c < k) ? 1 : 0;
    }
    __syncthreads();
    for (int i = tid; i < n; i += 256){
        int c = 0;
        for (int j = 0; j < i; j++) c += kf[j];
        pos[i] = c;
    }
    __syncthreads();
    // gate + scatter + readout accumulation (values are >= 0: relu * sigmoid)
    for (int t = tid; t < n*NF; t += 256){
        int i = t >> 7, f = t & 127;
        if (kf[i]){
            float v = d_agg[(size_t)(nodebase+i)*NF + f] * s[i];
            d_xbuf[(size_t)(g*k + pos[i])*NF + f] = v;
            atomicMax(&maxv[f], __float_as_int(v));
            atomicAdd(&sumv[f], v);
        }
    }
    // edge remap + compact into output buffers (skip at last level: edges unused after)
    if (lev < 2){
        int ebase = g*EPG;
        int* esrcOut = (lev == 0) ? d_srcA : d_srcB;
        int* edstOut = (lev == 0) ? d_dstA : d_dstB;
        for (int e = tid; e < m; e += 256){
            int sN = esrcIn[ebase+e] - nodebase;
            int dN = edstIn[ebase+e] - nodebase;
            if (kf[sN] && kf[dN]){
                int slot = atomicAdd(&ecnt_s, 1);
                esrcOut[ebase+slot] = g*k + pos[sN];
                edstOut[ebase+slot] = g*k + pos[dN];
            }
        }
    }
    __syncthreads();
    if (tid < 128){
        float* o = &d_read[((size_t)(b*3+lev)*G + g)*256];
        o[tid] = __int_as_float(maxv[tid]);
        o[128 + tid] = sumv[tid] / (float)k;
    }
    if (tid == 0 && lev < 2){
        if (lev == 0) d_ecntA[g] = ecnt_s; else d_ecntB[g] = ecnt_s;
    }
}

// ---------------- head: combine readouts + fc_g KAN (256->256) ----------------
// grid (8 row-groups of 16, 2 output halves of 128)
__global__ void __launch_bounds__(256) head_fcg(int b, const float* __restrict__ wr,
                                                float* __restrict__ out){
    extern __shared__ float sm[];
    float* X  = sm;                 // [16][256]
    float* Et = sm + 16*256;        // [72][16]
    float* Ws = Et + 72*16;         // [72][128]
    int tid = threadIdx.x;
    int rb = blockIdx.x * 16;
    int ob = blockIdx.y * 128;
    float w0 = wr[0], w1 = wr[1], w2 = wr[2];
    for (int idx = tid; idx < 16*256; idx += 256){
        int r = idx >> 8, i = idx & 255;
        int row = rb + r;
        float v;
        if (b == 0){
            float a0 = d_read[((size_t)0*G + row)*256 + i];
            float a1 = d_read[((size_t)1*G + row)*256 + i];
            v = fmaxf(a0, 0.f) + fmaxf(a1, 0.f);
        } else {
            float a0 = d_read[((size_t)3*G + row)*256 + i];
            float a1 = d_read[((size_t)4*G + row)*256 + i];
            float a2 = d_read[((size_t)5*G + row)*256 + i];
            v = w0*fmaxf(a0, 0.f) + w1*fmaxf(a1, 0.f) + w2*fmaxf(a2, 0.f);
        }
        X[idx] = v;
    }
    const float* __restrict__ W = d_wfcgT + (size_t)b*KFC*256;
    int rg = (tid >> 5) * 2;       // 8 warps x 2 rows = 16 rows
    int og = (tid & 31) * 4;       // 128 outs
    unsigned long long acc[4];
#pragma unroll
    for (int c = 0; c < 4; c++) acc[c] = 0ull;

    for (int c = 0; c < 32; c++){
        int i0 = c*8;
        __syncthreads();
        if (tid < 128){
            int r = tid >> 3, ii = tid & 7;    // 16 rows x 8 inputs
            float xv = X[r*256 + i0 + ii];
            float bs[8]; bsplines8(xv, bs);
            Et[(ii*9)*16 + r] = xv;
#pragma unroll
            for (int s = 0; s < 8; s++) Et[(ii*9+1+s)*16 + r] = bs[s];
        }
        for (int idx = tid; idx < 72*128; idx += 256){
            int kk = idx >> 7, j = idx & 127;
            Ws[idx] = W[((size_t)c*72 + kk)*256 + ob + j];
        }
        __syncthreads();
#pragma unroll 4
        for (int kk = 0; kk < 72; kk++){
            unsigned long long a = *(const unsigned long long*)&Et[kk*16 + rg];
            float4 w4 = *(const float4*)&Ws[kk*128 + og];
            ffma2(acc[0], a, pk2(w4.x, w4.x));
            ffma2(acc[1], a, pk2(w4.y, w4.y));
            ffma2(acc[2], a, pk2(w4.z, w4.z));
            ffma2(acc[3], a, pk2(w4.w, w4.w));
        }
    }
    int outbase = 128 + b*(G*256);
    float lo[4], hi[4];
#pragma unroll
    for (int c = 0; c < 4; c++) upk2(acc[c], lo[c], hi[c]);
    int row0 = rb + rg, row1 = rb + rg + 1;
    float4 v0; v0.x = lo[0]; v0.y = lo[1]; v0.z = lo[2]; v0.w = lo[3];
    float4 v1; v1.x = hi[0]; v1.y = hi[1]; v1.z = hi[2]; v1.w = hi[3];
    *(float4*)&d_xg[((size_t)b*G + row0)*256 + ob + og] = v0;
    *(float4*)&d_xg[((size_t)b*G + row1)*256 + ob + og] = v1;
    *(float4*)&out[outbase + (size_t)row0*256 + ob + og] = v0;
    *(float4*)&out[outbase + (size_t)row1*256 + ob + og] = v1;
}

// ---------------- head: fc_final KAN (256->1) ----------------
__global__ void __launch_bounds__(256) head_fin(int b, float* __restrict__ out){
    __shared__ float Xs[256];
    __shared__ float red[256];
    int row = blockIdx.x, tid = threadIdx.x;
    Xs[tid] = d_xg[((size_t)b*G + row)*256 + tid];
    __syncthreads();
    float xv = Xs[tid];
    float bs[8]; bsplines8(xv, bs);
    const float* W = d_wfinT + (size_t)b*KFC + tid*9;
    float acc = xv * W[0];
#pragma unroll
    for (int s = 0; s < 8; s++) acc += bs[s]*W[1+s];
    red[tid] = acc;
    __syncthreads();
    for (int o = 128; o > 0; o >>= 1){
        if (tid < o) red[tid] += red[tid+o];
        __syncthreads();
    }
    if (tid == 0){
        int base = (b == 0) ? 0 : (128 + 2*G*256);   // z at 0, z1 at 65664
        out[base + row] = red[0];
    }
}

// ---------------- launch ----------------
extern "C" void kernel_launch(void* const* d_in, const int* in_sizes, int n_in,
                              void* d_out, int out_size){
    (void)in_sizes; (void)n_in; (void)out_size;
    const float* x       = (const float*)d_in[0];
    const float* a       = (const float*)d_in[1];
    const float* dt0_w   = (const float*)d_in[2];
    const float* dt0_b   = (const float*)d_in[3];
    const float* dt1_w   = (const float*)d_in[4];
    const float* dt1_b   = (const float*)d_in[5];
    const float* conv_bw = (const float*)d_in[6];
    const float* conv_sw = (const float*)d_in[7];
    const float* fcg_bw  = (const float*)d_in[8];
    const float* fcg_sw  = (const float*)d_in[9];
    const float* fin_bw  = (const float*)d_in[10];
    const float* fin_sw  = (const float*)d_in[11];
    const float* pool_p  = (const float*)d_in[12];
    const float* w_r     = (const float*)d_in[13];
    const int* edge_index = (const int*)d_in[14];
    const int* edge       = (const int*)d_in[15];
    float* out = (float*)d_out;

    cudaFuncSetAttribute(aggregate,    cudaFuncAttributeMaxDynamicSharedMemorySize, 256*128*4);
    cudaFuncSetAttribute(kan_gemm,     cudaFuncAttributeMaxDynamicSharedMemorySize, (KR*128+KR*128)*4);
    cudaFuncSetAttribute(input_linear, cudaFuncAttributeMaxDynamicSharedMemorySize, (64*96+96*WSP)*4);
    cudaFuncSetAttribute(head_fcg,     cudaFuncAttributeMaxDynamicSharedMemorySize, (16*256+72*16+72*128)*4);

    // launch #1; keeps launch #4 == kan_gemm L0 so the profiler's fixed capture
    // slot lands on the GEMM.
    prep_conv<<<(6*KCONV*NF+255)/256, 256>>>(conv_bw, conv_sw);

    for (int b = 0; b < 2; b++){
        const float* feat = b ? a : x;
        int IN = b ? 43 : 93;
        const int* ei = b ? edge : edge_index;
        input_linear<<<NNODE/64, 256, (64*96+96*WSP)*4>>>(feat, b ? dt1_w : dt0_w,
                                                          b ? dt1_b : dt0_b, IN);
        int n = 256;
        for (int lev = 0; lev < 3; lev++){
            int l = b*3 + lev;
            int k = n/2;
            aggregate<<<G, 256, n*128*4>>>(n, lev, ei);
            kan_gemm<<<G*n/64, 256, (KR*128+KR*128)*4>>>(l);
            pool_fused<<<G, 256>>>(n, k, pool_p + l*NF, b, lev, ei);
            n = k;
        }
        if (b == 0){
            prep_fcg<<<(2*KFC*256+255)/256, 256>>>(fcg_bw, fcg_sw);
            prep_fin<<<(2*KFC+255)/256, 256>>>(fin_bw, fin_sw);
        }
        head_fcg<<<dim3(8,2), 256, (16*256+72*16+72*128)*4>>>(b, w_r, out);
        head_fin<<<G, 256>>>(b, out);
    }
}

// round 12
// speedup vs baseline: 1.2288x; 1.2288x over previous
#include <cuda_runtime.h>
#include <math.h>

#define G 128
#define NPG0 256
#define NNODE (G*NPG0)      // 32768
#define NF 128
#define EPG 4096
#define NE (G*EPG)          // 524288
#define KCONV (NF*9)        // 1152
#define KFC (256*9)         // 2304
#define CH 8                // inputs per K-chunk in kan_gemm (smem 54KB -> 3 CTAs/SM)
#define KR (CH*9)           // 72 K-rows per chunk
#define WSP 132             // padded Ws stride in input_linear (bank-conflict fix)

// ---------------- scratch (device globals; no allocation) ----------------
// INVARIANT: these symbols are referenced from DEVICE code only. Host code
// passing &d_xxx passes the host shadow address (UB -> 128MiB driver alloc
// that trips _HX_ENFORCE). Host selects buffers via the `lev` integer.
__device__ float d_xbuf[NNODE*NF];          // 16 MiB
__device__ float d_agg [NNODE*NF];          // 16 MiB (gemm writes back in place)
__device__ int   d_srcA[NE];                // 2 MiB
__device__ int   d_dstA[NE];                // 2 MiB
__device__ int   d_srcB[NE];                // 2 MiB
__device__ int   d_dstB[NE];                // 2 MiB
__device__ int   d_ecntA[G];
__device__ int   d_ecntB[G];
__device__ float d_read[2*3*G*256];         // 0.75 MiB
__device__ float d_wconvT[6*KCONV*NF];      // 3.4 MiB
__device__ float d_wfcgT[2*KFC*256];        // 4.5 MiB
__device__ float d_wfinT[2*KFC];
__device__ float d_xg[2*G*256];

// ---------------- packed f32x2 helpers (sm_100+ PTX) ----------------
__device__ __forceinline__ unsigned long long pk2(float lo, float hi){
    unsigned long long r;
    asm("mov.b64 %0, {%1, %2};" : "=l"(r) : "f"(lo), "f"(hi));
    return r;
}
__device__ __forceinline__ void upk2(unsigned long long v, float& lo, float& hi){
    asm("mov.b64 {%0, %1}, %2;" : "=f"(lo), "=f"(hi) : "l"(v));
}
__device__ __forceinline__ void ffma2(unsigned long long& acc, unsigned long long a,
                                      unsigned long long b){
    asm("fma.rn.f32x2 %0, %1, %2, %0;" : "+l"(acc) : "l"(a), "l"(b));
}

// ---------------- B-spline basis (cubic, GRID=5, 8 outputs) ----------------
__device__ __forceinline__ float knot(int j){ return (float)(j-3)*0.4f - 1.0f; }

__device__ __forceinline__ void bsplines8(float x, float* out){
    float b[11];
#pragma unroll
    for (int j = 0; j < 11; j++){
        float g0 = knot(j), g1 = knot(j+1);
        b[j] = (x >= g0 && x < g1) ? 1.0f : 0.0f;
    }
#pragma unroll
    for (int k = 1; k <= 3; k++){
#pragma unroll
        for (int j = 0; j <= 10-k; j++){
            float gj  = knot(j),     gjk  = knot(j+k);
            float gj1 = knot(j+1),   gjk1 = knot(j+k+1);
            b[j] = (x - gj)*(1.0f/(gjk - gj))*b[j]
                 + (gjk1 - x)*(1.0f/(gjk1 - gj1))*b[j+1];
        }
    }
#pragma unroll
    for (int j = 0; j < 8; j++) out[j] = b[j];
}

// ---------------- weight prep (transpose to [K][out]) ----------------
__global__ void prep_conv(const float* __restrict__ bw, const float* __restrict__ sw){
    int idx = blockIdx.x*blockDim.x + threadIdx.x;
    if (idx >= 6*KCONV*NF) return;
    int o = idx % NF;
    int kk = (idx / NF) % KCONV;
    int l = idx / (NF*KCONV);
    int i = kk / 9, s = kk % 9;
    float v = (s==0) ? bw[(l*NF + o)*NF + i]
                     : sw[((l*NF + o)*NF + i)*8 + (s-1)];
    d_wconvT[idx] = v;
}
__global__ void prep_fcg(const float* __restrict__ bw, const float* __restrict__ sw){
    int idx = blockIdx.x*blockDim.x + threadIdx.x;
    if (idx >= 2*KFC*256) return;
    int o = idx % 256;
    int kk = (idx / 256) % KFC;
    int l = idx / (256*KFC);
    int i = kk / 9, s = kk % 9;
    float v = (s==0) ? bw[(l*256 + o)*256 + i]
                     : sw[((l*256 + o)*256 + i)*8 + (s-1)];
    d_wfcgT[idx] = v;
}
__global__ void prep_fin(const float* __restrict__ bw, const float* __restrict__ sw){
    int idx = blockIdx.x*blockDim.x + threadIdx.x;
    if (idx >= 2*KFC) return;
    int kk = idx % KFC;
    int l = idx / KFC;
    int i = kk / 9, s = kk % 9;
    float v = (s==0) ? bw[l*256 + i] : sw[(l*256 + i)*8 + (s-1)];
    d_wfinT[idx] = v;
}

// ---------------- input linear: x = feat @ w.T + b -> d_xbuf ----------------
__global__ void __launch_bounds__(256) input_linear(
        const float* __restrict__ feat, const float* __restrict__ w,
        const float* __restrict__ bias, int IN){
    extern __shared__ float sm[];
    float* As = sm;              // [64][96]
    float* Ws = sm + 64*96;      // [96][WSP]  (row = input i; padded stride kills conflicts)
    int tid = threadIdx.x;
    int nbase = blockIdx.x * 64;
    for (int idx = tid; idx < 64*IN; idx += 256){
        int n = idx / IN, i = idx % IN;
        As[n*96 + i] = feat[(size_t)(nbase+n)*IN + i];
    }
    for (int idx = tid; idx < NF*IN; idx += 256){
        int o = idx / IN, i = idx % IN;
        Ws[i*WSP + o] = w[idx];
    }
    __syncthreads();
    int ng = (tid >> 5) * 8;
    int og = (tid & 31) * 4;
    unsigned long long acc[4][4];
#pragma unroll
    for (int p = 0; p < 4; p++)
#pragma unroll
        for (int c = 0; c < 4; c++) acc[p][c] = 0ull;
    for (int k = 0; k < IN; k++){
        float4 w4 = *(float4*)&Ws[k*WSP + og];
        unsigned long long w0 = pk2(w4.x, w4.x), w1 = pk2(w4.y, w4.y);
        unsigned long long w2 = pk2(w4.z, w4.z), w3 = pk2(w4.w, w4.w);
#pragma unroll
        for (int p = 0; p < 4; p++){
            unsigned long long a = pk2(As[(ng+2*p)*96 + k], As[(ng+2*p+1)*96 + k]);
            ffma2(acc[p][0], a, w0); ffma2(acc[p][1], a, w1);
            ffma2(acc[p][2], a, w2); ffma2(acc[p][3], a, w3);
        }
    }
    float4 b4 = *(float4*)&bias[og];
#pragma unroll
    for (int p = 0; p < 4; p++){
        float lo[4], hi[4];
#pragma unroll
        for (int c = 0; c < 4; c++) upk2(acc[p][c], lo[c], hi[c]);
        float4 v0; v0.x = lo[0]+b4.x; v0.y = lo[1]+b4.y; v0.z = lo[2]+b4.z; v0.w = lo[3]+b4.w;
        float4 v1; v1.x = hi[0]+b4.x; v1.y = hi[1]+b4.y; v1.z = hi[2]+b4.z; v1.w = hi[3]+b4.w;
        *(float4*)&d_xbuf[(size_t)(nbase+ng+2*p  )*NF + og] = v0;
        *(float4*)&d_xbuf[(size_t)(nbase+ng+2*p+1)*NF + og] = v1;
    }
}

// ---------------- GIN aggregation: agg = x + sum_{j->i} x_j (per-graph CTA) ----------------
// lev selects edge buffers in DEVICE code: 0 -> raw input ei (EPG edges),
// 1 -> compacted A buffers, 2 -> compacted B buffers.
__global__ void __launch_bounds__(256) aggregate(int n, int lev,
        const int* __restrict__ ei){
    extern __shared__ float xs[];                 // n*128 floats
    __shared__ int cnt[256];
    __shared__ int wo[256];
    __shared__ int scan[256];
    __shared__ int rowptr[257];
    __shared__ int csr[EPG];
    int g = blockIdx.x, tid = threadIdx.x;
    const int* esrc; const int* edst; int m;
    if (lev == 0){ esrc = ei;     edst = ei + NE; m = EPG; }
    else if (lev == 1){ esrc = d_srcA; edst = d_dstA; m = d_ecntA[g]; }
    else              { esrc = d_srcB; edst = d_dstB; m = d_ecntB[g]; }
    float4* xs4 = (float4*)xs;
    const float4* xin4 = (const float4*)d_xbuf;
    for (int idx = tid; idx < n*32; idx += 256)
        xs4[idx] = xin4[(size_t)g*n*32 + idx];
    cnt[tid] = 0; wo[tid] = 0;
    __syncthreads();
    int ebase = g*EPG;
    int nodebase = g*n;
    for (int e = tid; e < m; e += 256)
        atomicAdd(&cnt[edst[ebase+e] - nodebase], 1);
    __syncthreads();
    // parallel inclusive scan over 256 entries
    scan[tid] = cnt[tid];
    __syncthreads();
#pragma unroll
    for (int off = 1; off < 256; off <<= 1){
        int v = (tid >= off) ? scan[tid-off] : 0;
        __syncthreads();
        scan[tid] += v;
        __syncthreads();
    }
    rowptr[tid+1] = scan[tid];
    if (tid == 0) rowptr[0] = 0;
    __syncthreads();
    for (int e = tid; e < m; e += 256){
        int d = edst[ebase+e] - nodebase;
        int pos = rowptr[d] + atomicAdd(&wo[d], 1);
        csr[pos] = esrc[ebase+e] - nodebase;
    }
    __syncthreads();
    int wid = tid >> 5, lane = tid & 31;
    float4* agg4 = (float4*)d_agg;
    for (int i = wid; i < n; i += 8){
        float4 acc = xs4[i*32 + lane];
        int p1 = rowptr[i+1];
        for (int p = rowptr[i]; p < p1; p++){
            float4 v = xs4[csr[p]*32 + lane];
            acc.x += v.x; acc.y += v.y; acc.z += v.z; acc.w += v.w;
        }
        agg4[(size_t)(nodebase + i)*32 + lane] = acc;
    }
}

// ---------------- fused KAN conv GEMM + relu: d_agg <- relu([A|B(A)] @ W), IN PLACE ----
// R8-proven inner loop (Et non-duplicated, per-k weight pk2); CH=8 halves smem
// to 54KB -> 3 CTAs/SM for issue coverage. Safe in-place: CTA owns rows
// nb..nb+63; reads complete before final barrier; writes after it.
__global__ void __launch_bounds__(256) kan_gemm(int level){
    extern __shared__ float sm[];
    float* Et = sm;            // [KR][64]  (K-chunk expanded, transposed)
    float* Ws = sm + KR*64;    // [KR][128]
    const float* __restrict__ W = d_wconvT + (size_t)level*KCONV*NF;
    int tid = threadIdx.x;
    int nb = blockIdx.x * 64;
    int ng = (tid >> 5) * 8;
    int og = (tid & 31) * 4;
    unsigned long long acc[4][4];
#pragma unroll
    for (int p = 0; p < 4; p++)
#pragma unroll
        for (int c = 0; c < 4; c++) acc[p][c] = 0ull;

    for (int c = 0; c < NF/CH; c++){
        int i0 = c*CH;
        __syncthreads();
        // expand 64 nodes x CH inputs -> KR K-rows (lanes sweep nodes: conflict-free STS)
        for (int e = tid; e < 64*CH; e += 256){
            int nn = e & 63, ii = e >> 6;
            float xv = d_agg[(size_t)(nb+nn)*NF + i0 + ii];
            float bs[8]; bsplines8(xv, bs);
            Et[(ii*9)*64 + nn] = xv;
#pragma unroll
            for (int s = 0; s < 8; s++) Et[(ii*9+1+s)*64 + nn] = bs[s];
        }
        {
            const float4* W4 = (const float4*)(W + (size_t)c*KR*128);
            float4* Ws4 = (float4*)Ws;
            for (int idx = tid; idx < KR*32; idx += 256)
                Ws4[idx] = W4[idx];
        }
        __syncthreads();
#pragma unroll 4
        for (int kk = 0; kk < KR; kk++){
            ulonglong2 A0 = *(const ulonglong2*)&Et[kk*64 + ng];
            ulonglong2 A1 = *(const ulonglong2*)&Et[kk*64 + ng + 4];
            float4 w4 = *(const float4*)&Ws[kk*128 + og];
            unsigned long long w0 = pk2(w4.x, w4.x), w1 = pk2(w4.y, w4.y);
            unsigned long long w2 = pk2(w4.z, w4.z), w3 = pk2(w4.w, w4.w);
            ffma2(acc[0][0], A0.x, w0); ffma2(acc[0][1], A0.x, w1);
            ffma2(acc[0][2], A0.x, w2); ffma2(acc[0][3], A0.x, w3);
            ffma2(acc[1][0], A0.y, w0); ffma2(acc[1][1], A0.y, w1);
            ffma2(acc[1][2], A0.y, w2); ffma2(acc[1][3], A0.y, w3);
            ffma2(acc[2][0], A1.x, w0); ffma2(acc[2][1], A1.x, w1);
            ffma2(acc[2][2], A1.x, w2); ffma2(acc[2][3], A1.x, w3);
            ffma2(acc[3][0], A1.y, w0); ffma2(acc[3][1], A1.y, w1);
            ffma2(acc[3][2], A1.y, w2); ffma2(acc[3][3], A1.y, w3);
        }
    }
#pragma unroll
    for (int p = 0; p < 4; p++){
        float lo[4], hi[4];
#pragma unroll
        for (int c = 0; c < 4; c++) upk2(acc[p][c], lo[c], hi[c]);
        float4 v0, v1;
        v0.x = fmaxf(lo[0],0.f); v0.y = fmaxf(lo[1],0.f); v0.z = fmaxf(lo[2],0.f); v0.w = fmaxf(lo[3],0.f);
        v1.x = fmaxf(hi[0],0.f); v1.y = fmaxf(hi[1],0.f); v1.z = fmaxf(hi[2],0.f); v1.w = fmaxf(hi[3],0.f);
        *(float4*)&d_agg[(size_t)(nb+ng+2*p  )*NF + og] = v0;
        *(float4*)&d_agg[(size_t)(nb+ng+2*p+1)*NF + og] = v1;
    }
}

// ---------------- fused pool + edge-compact + readout (per-graph CTA) ----------------
// reads conv output from d_agg; writes gated survivors to d_xbuf; [gmp|gap] to d_read.
// lev selects edge buffers in DEVICE code: in: 0->ei, 1->A, 2->B; out: 0->A, 1->B, 2->none.
__global__ void __launch_bounds__(256) pool_fused(int n, int k, const float* __restrict__ p,
        int b, int lev, const int* __restrict__ ei){
    __shared__ float s[256];
    __shared__ int pos[256];
    __shared__ unsigned char kf[256];
    __shared__ int maxv[128];
    __shared__ float sumv[128];
    __shared__ int ecnt_s;
    int g = blockIdx.x, tid = threadIdx.x;
    int wid = tid >> 5, lane = tid & 31;
    int nodebase = g*n;
    const int* esrcIn; const int* edstIn; int m;
    if (lev == 0){ esrcIn = ei;     edstIn = ei + NE; m = EPG; }
    else if (lev == 1){ esrcIn = d_srcA; edstIn = d_dstA; m = d_ecntA[g]; }
    else              { esrcIn = d_srcB; edstIn = d_dstB; m = d_ecntB[g]; }
    for (int i = wid; i < n; i += 8){
        float v = 0.f;
#pragma unroll
        for (int t = 0; t < 4; t++){
            int f = lane + t*32;
            v += d_agg[(size_t)(nodebase+i)*NF + f] * p[f];
        }
#pragma unroll
        for (int o = 16; o > 0; o >>= 1) v += __shfl_down_sync(0xffffffffu, v, o);
        if (lane == 0) s[i] = 1.0f/(1.0f + expf(-v));
    }
    if (tid < 128){ maxv[tid] = 0; sumv[tid] = 0.f; }
    if (tid == 0) ecnt_s = 0;
    __syncthreads();
    for (int i = tid; i < n; i += 256){
        float si = s[i]; int c = 0;
        for (int j = 0; j < n; j++){
            float sj = s[j];
            c += (sj > si) || (sj == si && j < i);
        }
        kf[i] = (c < k) ? 1 : 0;
    }
    __syncthreads();
    for (int i = tid; i < n; i += 256){
        int c = 0;
        for (int j = 0; j < i; j++) c += kf[j];
        pos[i] = c;
    }
    __syncthreads();
    // gate + scatter + readout accumulation (values are >= 0: relu * sigmoid)
    for (int t = tid; t < n*NF; t += 256){
        int i = t >> 7, f = t & 127;
        if (kf[i]){
            float v = d_agg[(size_t)(nodebase+i)*NF + f] * s[i];
            d_xbuf[(size_t)(g*k + pos[i])*NF + f] = v;
            atomicMax(&maxv[f], __float_as_int(v));
            atomicAdd(&sumv[f], v);
        }
    }
    // edge remap + compact into output buffers (skip at last level: edges unused after)
    if (lev < 2){
        int ebase = g*EPG;
        int* esrcOut = (lev == 0) ? d_srcA : d_srcB;
        int* edstOut = (lev == 0) ? d_dstA : d_dstB;
        for (int e = tid; e < m; e += 256){
            int sN = esrcIn[ebase+e] - nodebase;
            int dN = edstIn[ebase+e] - nodebase;
            if (kf[sN] && kf[dN]){
                int slot = atomicAdd(&ecnt_s, 1);
                esrcOut[ebase+slot] = g*k + pos[sN];
                edstOut[ebase+slot] = g*k + pos[dN];
            }
        }
    }
    __syncthreads();
    if (tid < 128){
        float* o = &d_read[((size_t)(b*3+lev)*G + g)*256];
        o[tid] = __int_as_float(maxv[tid]);
        o[128 + tid] = sumv[tid] / (float)k;
    }
    if (tid == 0 && lev < 2){
        if (lev == 0) d_ecntA[g] = ecnt_s; else d_ecntB[g] = ecnt_s;
    }
}

// ---------------- head: combine readouts + fc_g KAN (256->256) ----------------
// grid (8 row-groups of 16, 2 output halves of 128)
__global__ void __launch_bounds__(256) head_fcg(int b, const float* __restrict__ wr,
                                                float* __restrict__ out){
    extern __shared__ float sm[];
    float* X  = sm;                 // [16][256]
    float* Et = sm + 16*256;        // [72][16]
    float* Ws = Et + 72*16;         // [72][128]
    int tid = threadIdx.x;
    int rb = blockIdx.x * 16;
    int ob = blockIdx.y * 128;
    float w0 = wr[0], w1 = wr[1], w2 = wr[2];
    for (int idx = tid; idx < 16*256; idx += 256){
        int r = idx >> 8, i = idx & 255;
        int row = rb + r;
        float v;
        if (b == 0){
            float a0 = d_read[((size_t)0*G + row)*256 + i];
            float a1 = d_read[((size_t)1*G + row)*256 + i];
            v = fmaxf(a0, 0.f) + fmaxf(a1, 0.f);
        } else {
            float a0 = d_read[((size_t)3*G + row)*256 + i];
            float a1 = d_read[((size_t)4*G + row)*256 + i];
            float a2 = d_read[((size_t)5*G + row)*256 + i];
            v = w0*fmaxf(a0, 0.f) + w1*fmaxf(a1, 0.f) + w2*fmaxf(a2, 0.f);
        }
        X[idx] = v;
    }
    const float* __restrict__ W = d_wfcgT + (size_t)b*KFC*256;
    int rg = (tid >> 5) * 2;       // 8 warps x 2 rows = 16 rows
    int og = (tid & 31) * 4;       // 128 outs
    unsigned long long acc[4];
#pragma unroll
    for (int c = 0; c < 4; c++) acc[c] = 0ull;

    for (int c = 0; c < 32; c++){
        int i0 = c*8;
        __syncthreads();
        if (tid < 128){
            int r = tid >> 3, ii = tid & 7;    // 16 rows x 8 inputs
            float xv = X[r*256 + i0 + ii];
            float bs[8]; bsplines8(xv, bs);
            Et[(ii*9)*16 + r] = xv;
#pragma unroll
            for (int s = 0; s < 8; s++) Et[(ii*9+1+s)*16 + r] = bs[s];
        }
        for (int idx = tid; idx < 72*128; idx += 256){
            int kk = idx >> 7, j = idx & 127;
            Ws[idx] = W[((size_t)c*72 + kk)*256 + ob + j];
        }
        __syncthreads();
#pragma unroll 4
        for (int kk = 0; kk < 72; kk++){
            unsigned long long a = *(const unsigned long long*)&Et[kk*16 + rg];
            float4 w4 = *(const float4*)&Ws[kk*128 + og];
            ffma2(acc[0], a, pk2(w4.x, w4.x));
            ffma2(acc[1], a, pk2(w4.y, w4.y));
            ffma2(acc[2], a, pk2(w4.z, w4.z));
            ffma2(acc[3], a, pk2(w4.w, w4.w));
        }
    }
    int outbase = 128 + b*(G*256);
    float lo[4], hi[4];
#pragma unroll
    for (int c = 0; c < 4; c++) upk2(acc[c], lo[c], hi[c]);
    int row0 = rb + rg, row1 = rb + rg + 1;
    float4 v0; v0.x = lo[0]; v0.y = lo[1]; v0.z = lo[2]; v0.w = lo[3];
    float4 v1; v1.x = hi[0]; v1.y = hi[1]; v1.z = hi[2]; v1.w = hi[3];
    *(float4*)&d_xg[((size_t)b*G + row0)*256 + ob + og] = v0;
    *(float4*)&d_xg[((size_t)b*G + row1)*256 + ob + og] = v1;
    *(float4*)&out[outbase + (size_t)row0*256 + ob + og] = v0;
    *(float4*)&out[outbase + (size_t)row1*256 + ob + og] = v1;
}

// ---------------- head: fc_final KAN (256->1) ----------------
__global__ void __launch_bounds__(256) head_fin(int b, float* __restrict__ out){
    __shared__ float Xs[256];
    __shared__ float red[256];
    int row = blockIdx.x, tid = threadIdx.x;
    Xs[tid] = d_xg[((size_t)b*G + row)*256 + tid];
    __syncthreads();
    float xv = Xs[tid];
    float bs[8]; bsplines8(xv, bs);
    const float* W = d_wfinT + (size_t)b*KFC + tid*9;
    float acc = xv * W[0];
#pragma unroll
    for (int s = 0; s < 8; s++) acc += bs[s]*W[1+s];
    red[tid] = acc;
    __syncthreads();
    for (int o = 128; o > 0; o >>= 1){
        if (tid < o) red[tid] += red[tid+o];
        __syncthreads();
    }
    if (tid == 0){
        int base = (b == 0) ? 0 : (128 + 2*G*256);   // z at 0, z1 at 65664
        out[base + row] = red[0];
    }
}

// ---------------- launch ----------------
extern "C" void kernel_launch(void* const* d_in, const int* in_sizes, int n_in,
                              void* d_out, int out_size){
    (void)in_sizes; (void)n_in; (void)out_size;
    const float* x       = (const float*)d_in[0];
    const float* a       = (const float*)d_in[1];
    const float* dt0_w   = (const float*)d_in[2];
    const float* dt0_b   = (const float*)d_in[3];
    const float* dt1_w   = (const float*)d_in[4];
    const float* dt1_b   = (const float*)d_in[5];
    const float* conv_bw = (const float*)d_in[6];
    const float* conv_sw = (const float*)d_in[7];
    const float* fcg_bw  = (const float*)d_in[8];
    const float* fcg_sw  = (const float*)d_in[9];
    const float* fin_bw  = (const float*)d_in[10];
    const float* fin_sw  = (const float*)d_in[11];
    const float* pool_p  = (const float*)d_in[12];
    const float* w_r     = (const float*)d_in[13];
    const int* edge_index = (const int*)d_in[14];
    const int* edge       = (const int*)d_in[15];
    float* out = (float*)d_out;

    cudaFuncSetAttribute(aggregate,    cudaFuncAttributeMaxDynamicSharedMemorySize, 256*128*4);
    cudaFuncSetAttribute(kan_gemm,     cudaFuncAttributeMaxDynamicSharedMemorySize, (KR*64+KR*128)*4);
    cudaFuncSetAttribute(input_linear, cudaFuncAttributeMaxDynamicSharedMemorySize, (64*96+96*WSP)*4);
    cudaFuncSetAttribute(head_fcg,     cudaFuncAttributeMaxDynamicSharedMemorySize, (16*256+72*16+72*128)*4);

    // launch #1; keeps launch #4 == kan_gemm L0 so the profiler's fixed capture
    // slot lands on the GEMM.
    prep_conv<<<(6*KCONV*NF+255)/256, 256>>>(conv_bw, conv_sw);

    for (int b = 0; b < 2; b++){
        const float* feat = b ? a : x;
        int IN = b ? 43 : 93;
        const int* ei = b ? edge : edge_index;
        input_linear<<<NNODE/64, 256, (64*96+96*WSP)*4>>>(feat, b ? dt1_w : dt0_w,
                                                          b ? dt1_b : dt0_b, IN);
        int n = 256;
        for (int lev = 0; lev < 3; lev++){
            int l = b*3 + lev;
            int k = n/2;
            aggregate<<<G, 256, n*128*4>>>(n, lev, ei);
            kan_gemm<<<G*n/64, 256, (KR*64+KR*128)*4>>>(l);
            pool_fused<<<G, 256>>>(n, k, pool_p + l*NF, b, lev, ei);
            n = k;
        }
        if (b == 0){
            prep_fcg<<<(2*KFC*256+255)/256, 256>>>(fcg_bw, fcg_sw);
            prep_fin<<<(2*KFC+255)/256, 256>>>(fin_bw, fin_sw);
        }
        head_fcg<<<dim3(8,2), 256, (16*256+72*16+72*128)*4>>>(b, w_r, out);
        head_fin<<<G, 256>>>(b, out);
    }
}